// round 13
// baseline (speedup 1.0000x reference)
#include <cuda_runtime.h>

#define NATOMS_MAX 20000
#define NEDGES_MAX 500000
#define LOG2E 1.4426950408889634f
#define PI_OVER_CUT (3.14159265358979323846f / 6.0f)

// scratch (accumulators + packed edge records)
__device__ uint2 g_rec[NEDGES_MAX];        // {D, tgt|s<<20|t<<21}
__device__ float g_g2s[NATOMS_MAX * 16];   // [n][src_species][8 etas]
__device__ float g_g4s[NATOMS_MAX * 48];   // [n][t][ii*5+p] moments, 64B t-blocks

__device__ __forceinline__ float ex2(float x) {
    float y; asm("ex2.approx.ftz.f32 %0, %1;" : "=f"(y) : "f"(x)); return y;
}
__device__ __forceinline__ void red4(float* p, float a, float b, float c, float d) {
    asm volatile("red.global.add.v4.f32 [%0], {%1,%2,%3,%4};"
                 :: "l"(p), "f"(a), "f"(b), "f"(c), "f"(d) : "memory");
}
__device__ __forceinline__ float fc(float R) {
    return fmaf(0.5f, __cosf(PI_OVER_CUT * R), 0.5f);
}
__device__ __forceinline__ unsigned pk(int tgt, int s, int t) {
    return (unsigned)tgt | ((unsigned)s << 20) | ((unsigned)t << 21);
}

__device__ __forceinline__ void rec_scalar(const int* an, const int* ei,
                                           const float* D, int E, int e) {
    int src = __ldg(ei + e);
    int tgt = __ldg(ei + E + e);
    int s = __ldg(an + src);
    int t = __ldg(an + tgt);
    float d = __ldg(D + e);
    g_rec[e] = make_uint2(__float_as_uint(d), pk(tgt, s, t));
}

// k1: [0, recB): build packed records, 4 edges/thread via 128-bit streams;
//     [recB, recB+zeroB): zero accumulators (float4)
__global__ void __launch_bounds__(256) rec_zero_k(const int* __restrict__ an,
                                                  const int* __restrict__ ei,
                                                  const float* __restrict__ D,
                                                  int E, int E4, int recB, int N) {
    int b = blockIdx.x;
    if (b < recB) {
        int i = b * 256 + threadIdx.x;
        if (i < E4) {
            const int4* ei4 = (const int4*)ei;
            int4 s4 = __ldg(ei4 + i);
            int4 t4 = __ldg(ei4 + E4 + i);
            float4 d4 = __ldg((const float4*)D + i);
            int a0 = __ldg(an + s4.x), a1 = __ldg(an + s4.y);
            int a2 = __ldg(an + s4.z), a3 = __ldg(an + s4.w);
            int b0 = __ldg(an + t4.x), b1 = __ldg(an + t4.y);
            int b2 = __ldg(an + t4.z), b3 = __ldg(an + t4.w);
            uint4 r0 = make_uint4(__float_as_uint(d4.x), pk(t4.x, a0, b0),
                                  __float_as_uint(d4.y), pk(t4.y, a1, b1));
            uint4 r1 = make_uint4(__float_as_uint(d4.z), pk(t4.z, a2, b2),
                                  __float_as_uint(d4.w), pk(t4.w, a3, b3));
            uint4* recs = (uint4*)g_rec;
            recs[i * 2]     = r0;
            recs[i * 2 + 1] = r1;
        }
        if (b == 0) {
            int e = E4 * 4 + threadIdx.x;
            if (e < E) rec_scalar(an, ei, D, E, e);
        }
    } else {
        int i = (b - recB) * 256 + threadIdx.x;
        float4 z = make_float4(0.f, 0.f, 0.f, 0.f);
        int n4g2 = N * 4;
        if (i < n4g2) reinterpret_cast<float4*>(g_g2s)[i] = z;
        int n4g4 = N * 12;
#pragma unroll
        for (int r = 0; r < 3; r++) {
            int j = i + r * n4g2;
            if (j < n4g4) reinterpret_cast<float4*>(g_g4s)[j] = z;
        }
    }
}

// G4 inner body (after loads): compute + moment scatter
__device__ __forceinline__ void g4_body(uint2 rb, uint2 rc, float cph,
                                        const float* __restrict__ g4_etas) {
    float Rba = __uint_as_float(rb.x);
    float Rca = __uint_as_float(rc.x);
    if (Rba >= 6.0f || Rca >= 6.0f) return;

    float Rbc2 = fmaf(Rba, Rba, fmaf(Rca, Rca, -2.0f * Rba * Rca * cph));
    float Rbc = sqrtf(fmaxf(Rbc2, 1e-12f));
    if (Rbc >= 6.0f) return;

    int aidx = rb.y & 0xFFFFF;
    int A    = (rb.y >> 21) & 1;
    int sb   = (rb.y >> 20) & 1;
    int sc   = (rc.y >> 20) & 1;
    int t = sb + sc;
    int k4 = A * 3 + t;

    float cut3 = fc(Rba) * fc(Rca) * fc(Rbc);
    float r2 = Rbc2 + Rba * Rba + Rca * Rca;

    const float* eta = g4_etas + k4 * 3;
    float mr2 = -r2 * LOG2E;
    float rad[3];
#pragma unroll
    for (int ii = 0; ii < 3; ii++) rad[ii] = ex2(mr2 * __ldg(eta + ii)) * cut3;

    float c1 = cph;
    float c2 = c1 * c1;
    float c3 = c2 * c1;
    float c4 = c2 * c2;
    float cp[5] = { 1.0f, c1, c2, c3, c4 };

    float v[15];
#pragma unroll
    for (int ii = 0; ii < 3; ii++)
#pragma unroll
        for (int p = 0; p < 5; p++)
            v[ii * 5 + p] = rad[ii] * cp[p];

    float* o = g_g4s + aidx * 48 + t * 16;   // 64B block: exactly 2 sectors
    red4(o,      v[0],  v[1],  v[2],  v[3]);
    red4(o + 4,  v[4],  v[5],  v[6],  v[7]);
    red4(o + 8,  v[8],  v[9],  v[10], v[11]);
    red4(o + 12, v[12], v[13], v[14], 0.0f);
}

__device__ __forceinline__ void g4_pair(int ba0, int ca0, float c0,
                                        int ba1, int ca1, float c1,
                                        const float* __restrict__ g4_etas) {
    bool q0 = ba0 > ca0;
    bool q1 = ba1 > ca1;
    uint2 rb0, rc0, rb1, rc1;
    if (q0) { rb0 = g_rec[ba0]; rc0 = g_rec[ca0]; }
    if (q1) { rb1 = g_rec[ba1]; rc1 = g_rec[ca1]; }
    if (q0) g4_body(rb0, rc0, c0, g4_etas);
    if (q1) g4_body(rb1, rc1, c1, g4_etas);
}

__device__ __forceinline__ void g2_body(unsigned du, unsigned meta,
                                        const float* __restrict__ g2_etas) {
    float d = __uint_as_float(du);
    int tgt = meta & 0xFFFFF;
    int s   = (meta >> 20) & 1;
    int t   = (meta >> 21) & 1;
    float cut = fc(d);
    float md2 = -d * d * LOG2E;
    const float* eta = g2_etas + (s * 2 + t) * 8;
    float v[8];
#pragma unroll
    for (int k = 0; k < 8; k++) v[k] = cut * ex2(md2 * __ldg(eta + k));
    float* o = g_g2s + tgt * 16 + s * 8;
    red4(o,     v[0], v[1], v[2], v[3]);
    red4(o + 4, v[4], v[5], v[6], v[7]);
}

// k2: [0, g4B): G4, 4 triplets/thread (128-bit front loads, 2x2 pair processing);
//     [g4B, ...): G2, 2 edges/thread streaming records as uint4
__global__ void __launch_bounds__(256) fused_k(const int* __restrict__ id3_ba,
                                               const int* __restrict__ id3_ca,
                                               const float* __restrict__ cosphi,
                                               const float* __restrict__ g4_etas,
                                               const float* __restrict__ g2_etas,
                                               int T, int T4, int E, int E2, int g4B) {
    int b = blockIdx.x;
    if (b < g4B) {
        int i = b * 256 + threadIdx.x;
        if (i < T4) {
            int4 ba4 = __ldg((const int4*)id3_ba + i);
            int4 ca4 = __ldg((const int4*)id3_ca + i);
            float4 c4 = __ldg((const float4*)cosphi + i);
            g4_pair(ba4.x, ca4.x, c4.x, ba4.y, ca4.y, c4.y, g4_etas);
            g4_pair(ba4.z, ca4.z, c4.z, ba4.w, ca4.w, c4.w, g4_etas);
        }
        if (b == 0) {
            int t = T4 * 4 + threadIdx.x;
            if (t < T) {
                int ba = __ldg(id3_ba + t);
                int ca = __ldg(id3_ca + t);
                if (ba > ca)
                    g4_body(g_rec[ba], g_rec[ca], __ldg(cosphi + t), g4_etas);
            }
        }
    } else {
        int e2 = (b - g4B) * 256 + threadIdx.x;
        if (e2 < E2) {
            uint4 rr = __ldg((const uint4*)g_rec + e2);
            g2_body(rr.x, rr.y, g2_etas);
            g2_body(rr.z, rr.w, g2_etas);
        }
        if (b == g4B) {
            int e = E2 * 2 + threadIdx.x;
            if (e < E) {
                uint2 r = g_rec[e];
                g2_body(r.x, r.y, g2_etas);
            }
        }
    }
}

// k3: reconstruct final [N,70]; one float2/thread; branch-free binomial reconstruction
__global__ void __launch_bounds__(256) combine_k(float2* __restrict__ out, int n2_total) {
    int i = blockIdx.x * blockDim.x + threadIdx.x;
    if (i >= n2_total) return;
    int n = i / 35;
    int c = (i - n * 35) * 2;   // even col; pair never spans g2/g4 boundary
    float2 v;
    if (c < 16) {
        const float* g2 = g_g2s + n * 16;
        v.x = g2[(c & 1) * 8 + (c >> 1)];
        v.y = g2[((c + 1) & 1) * 8 + ((c + 1) >> 1)];
    } else {
        const float* g4 = g_g4s + n * 48;
        float r[2];
#pragma unroll
        for (int q = 0; q < 2; q++) {
            int idx = c - 16 + q;          // idx = m*3 + t ; m = (ii*2+j)*3 + kk
            int t = idx % 3;
            int m = idx / 3;
            int ii = m / 6;
            int j  = (m / 3) & 1;          // lambda: 0 -> -1, 1 -> +1
            int kk = m % 3;                // zeta: 1, 2, 4
            const float* s = g4 + t * 16 + ii * 5;
            float S0 = s[0], S1 = s[1], S2 = s[2], S3 = s[3], S4 = s[4];
            float lS1 = j ? S1 : -S1;
            float lS3 = j ? S3 : -S3;
            float v1 = S0 + lS1;
            float v2 = 0.5f * fmaf(2.0f, lS1, S0 + S2);
            float v4 = 0.125f * (fmaf(6.0f, S2, S0 + S4) + 4.0f * (lS1 + lS3));
            r[q] = (kk == 0) ? v1 : ((kk == 1) ? v2 : v4);
        }
        v.x = r[0];
        v.y = r[1];
    }
    out[i] = v;
}

extern "C" void kernel_launch(void* const* d_in, const int* in_sizes, int n_in,
                              void* d_out, int out_size) {
    const int*   an       = (const int*)  d_in[0];
    const int*   ei       = (const int*)  d_in[1];
    const float* D        = (const float*)d_in[2];
    const int*   id3_ba   = (const int*)  d_in[3];
    const int*   id3_ca   = (const int*)  d_in[4];
    const float* cosphi   = (const float*)d_in[5];
    const float* g2_etas  = (const float*)d_in[6];
    const float* g4_etas  = (const float*)d_in[7];

    int E = in_sizes[2];
    int T = in_sizes[3];
    int N = in_sizes[0];

    int E4 = E / 4;                 // vector part (E%4 tail handled in block 0)
    int recB  = (E4 + 255) / 256;
    if (recB < 1) recB = 1;
    int zeroB = (N * 4 + 255) / 256;
    rec_zero_k<<<recB + zeroB, 256>>>(an, ei, D, E, E4, recB, N);

    int T4 = T / 4;
    int E2 = E / 2;
    int g4B = (T4 + 255) / 256;
    if (g4B < 1) g4B = 1;
    int g2B = (E2 + 255) / 256;
    if (g2B < 1) g2B = 1;
    fused_k<<<g4B + g2B, 256>>>(id3_ba, id3_ca, cosphi, g4_etas, g2_etas,
                                T, T4, E, E2, g4B);

    int n2 = out_size / 2;
    combine_k<<<(n2 + 255) / 256, 256>>>((float2*)d_out, n2);
}